// round 10
// baseline (speedup 1.0000x reference)
#include <cuda_runtime.h>
#include <cuda_fp16.h>
#include <mma.h>
#include <cstdint>

using namespace nvcuda;

// out[8192,4096] = x[8192,4096] @ tanh(blocks*mask); blocks = 16 diag blocks 256x256.
// fp16 single-pass HMMA, single-sync software pipeline:
//   Stage 1: tanh + transpose blocks -> g_B [blk][n][k] fp16.
//   Stage 2: CTA tile 128x256 (full block N), K=256 in 4 chunks of 64,
//            double-buffered smem; per chunk: cp.async B(c+1), MMA(c),
//            convert A(c+1), LDG A(c+2), one __syncthreads.

#define LAYER 4096
#define NROWS 8192
#define NBLK  16
#define BSZ   256
#define KCH   64
#define LDA   72   // fp16 elems; 144 B row stride
#define LDB   72

__device__ __align__(16) __half g_B[NBLK * BSZ * BSZ];  // [blk][n][k]

__device__ __forceinline__ uint32_t smem_u32(const void* p) {
    uint32_t a;
    asm("{ .reg .u64 t; cvta.to.shared.u64 t, %1; cvt.u32.u64 %0, t; }" : "=r"(a) : "l"(p));
    return a;
}
__device__ __forceinline__ uint32_t h2u(__half2 h) {
    return *reinterpret_cast<uint32_t*>(&h);
}

// ---------------- Stage 1: tanh + transpose blocks ----------------
__global__ __launch_bounds__(256) void prep_B(const float* __restrict__ blocks) {
    __shared__ float v[32][BSZ + 1];
    const int kt  = blockIdx.x;   // 0..7
    const int blk = blockIdx.y;   // 0..15
    const int tid = threadIdx.x;

    #pragma unroll
    for (int i = 0; i < 32; i++) {
        int idx = tid + i * 256;
        int k = idx >> 8, n = idx & 255;
        v[k][n] = blocks[(size_t)(blk * BSZ + kt * 32 + k) * LAYER + (size_t)(blk * BSZ + n)];
    }
    __syncthreads();

    const int n = tid;
    uint32_t w[16];
    #pragma unroll
    for (int k2 = 0; k2 < 16; k2++) {
        float t0 = tanhf(v[2 * k2][n]);
        float t1 = tanhf(v[2 * k2 + 1][n]);
        w[k2] = h2u(__floats2half2_rn(t0, t1));
    }
    size_t base = (size_t)(blk * BSZ + n) * BSZ + kt * 32;  // [blk][n][k]
    #pragma unroll
    for (int q = 0; q < 4; q++)
        *reinterpret_cast<uint4*>(&g_B[base + q * 8]) =
            make_uint4(w[4 * q], w[4 * q + 1], w[4 * q + 2], w[4 * q + 3]);
}

// ---------------- Stage 2: pipelined HMMA GEMM ----------------
// dyn smem: sA0 18432 | sB0 36864 | sA1 18432 | sB1 36864 = 110592 B
#define SMA0 0
#define SMB0 18432
#define SMA1 55296
#define SMB1 73728
#define SM_TOTAL 110592

__global__ void __launch_bounds__(512, 1) bd_hmma(const float* __restrict__ x,
                                                  float* __restrict__ out) {
    extern __shared__ __align__(16) char smem[];
    const uint32_t sbase = smem_u32(smem);
    const int tid = threadIdx.x;
    const int w   = tid >> 5;
    const int wm  = w & 3;        // 0..3 -> 32-row band
    const int wn  = w >> 2;       // 0..3 -> 64-col band
    const int mTile = blockIdx.x; // 0..63
    const int blk   = blockIdx.y; // 0..15

    const float*  Asrc = x + (size_t)mTile * 128 * LAYER + (size_t)blk * BSZ;
    const __half* Bsrc = g_B + (size_t)blk * BSZ * BSZ;

    wmma::fragment<wmma::accumulator, 16, 16, 16, float> acc[2][4];
    #pragma unroll
    for (int i = 0; i < 2; i++)
        #pragma unroll
        for (int j = 0; j < 4; j++) wmma::fill_fragment(acc[i][j], 0.0f);

    float4 aReg[2][4];

    __half* sAbuf[2] = { reinterpret_cast<__half*>(smem + SMA0),
                         reinterpret_cast<__half*>(smem + SMA1) };
    __half* sBbuf[2] = { reinterpret_cast<__half*>(smem + SMB0),
                         reinterpret_cast<__half*>(smem + SMB1) };

    // ---- prologue ----
    #pragma unroll
    for (int i = 0; i < 4; i++) {                       // A chunk 0 -> regs
        int f = tid + i * 512;
        int row = f >> 4, c4 = f & 15;
        aReg[0][i] = *reinterpret_cast<const float4*>(Asrc + (size_t)row * LAYER + c4 * 4);
    }
    #pragma unroll
    for (int i = 0; i < 4; i++) {                       // B chunk 0 -> sB0
        int u = tid + i * 512;
        int n = u >> 3, q = u & 7;
        uint32_t dst = sbase + SMB0 + (uint32_t)(n * LDB + q * 8) * 2;
        const __half* src = Bsrc + (size_t)n * BSZ + q * 8;
        asm volatile("cp.async.ca.shared.global [%0], [%1], 16;" :: "r"(dst), "l"(src) : "memory");
    }
    asm volatile("cp.async.commit_group;" ::: "memory");
    #pragma unroll
    for (int i = 0; i < 4; i++) {                       // convert A0 -> sA0
        int f = tid + i * 512;
        int row = f >> 4, c4 = f & 15;
        __half2 h01 = __floats2half2_rn(aReg[0][i].x, aReg[0][i].y);
        __half2 h23 = __floats2half2_rn(aReg[0][i].z, aReg[0][i].w);
        *reinterpret_cast<uint2*>(sAbuf[0] + row * LDA + c4 * 4) = make_uint2(h2u(h01), h2u(h23));
    }
    #pragma unroll
    for (int i = 0; i < 4; i++) {                       // A chunk 1 -> regs
        int f = tid + i * 512;
        int row = f >> 4, c4 = f & 15;
        aReg[1][i] = *reinterpret_cast<const float4*>(Asrc + (size_t)row * LAYER + KCH + c4 * 4);
    }
    asm volatile("cp.async.wait_group 0;" ::: "memory");
    __syncthreads();

    // ---- mainloop (fully unrolled, one sync per chunk) ----
    #pragma unroll
    for (int c = 0; c < 4; c++) {
        __half* sA = sAbuf[c & 1];
        __half* sB = sBbuf[c & 1];

        // (1) start B(c+1) copy into the other buffer (safe: last read at c-1, synced)
        if (c < 3) {
            uint32_t dstB = sbase + (((c + 1) & 1) ? SMB1 : SMB0);
            #pragma unroll
            for (int i = 0; i < 4; i++) {
                int u = tid + i * 512;
                int n = u >> 3, q = u & 7;
                uint32_t dst = dstB + (uint32_t)(n * LDB + q * 8) * 2;
                const __half* src = Bsrc + (size_t)n * BSZ + (c + 1) * KCH + q * 8;
                asm volatile("cp.async.ca.shared.global [%0], [%1], 16;" :: "r"(dst), "l"(src) : "memory");
            }
            asm volatile("cp.async.commit_group;" ::: "memory");
        }

        // (2) MMA ks 0..1
        #pragma unroll
        for (int ks = 0; ks < 2; ks++) {
            wmma::fragment<wmma::matrix_a, 16, 16, 16, __half, wmma::row_major> a0, a1;
            wmma::load_matrix_sync(a0, sA + (wm * 32)      * LDA + ks * 16, LDA);
            wmma::load_matrix_sync(a1, sA + (wm * 32 + 16) * LDA + ks * 16, LDA);
            #pragma unroll
            for (int j = 0; j < 4; j++) {
                wmma::fragment<wmma::matrix_b, 16, 16, 16, __half, wmma::col_major> b;
                wmma::load_matrix_sync(b, sB + ks * 16 + (wn * 64 + j * 16) * LDB, LDB);
                wmma::mma_sync(acc[0][j], a0, b, acc[0][j]);
                wmma::mma_sync(acc[1][j], a1, b, acc[1][j]);
            }
        }

        // (3) convert A(c+1) -> other sA buffer (overlaps with MMA)
        if (c < 3) {
            __half* sAn = sAbuf[(c + 1) & 1];
            #pragma unroll
            for (int i = 0; i < 4; i++) {
                int f = tid + i * 512;
                int row = f >> 4, c4 = f & 15;
                __half2 h01 = __floats2half2_rn(aReg[(c + 1) & 1][i].x, aReg[(c + 1) & 1][i].y);
                __half2 h23 = __floats2half2_rn(aReg[(c + 1) & 1][i].z, aReg[(c + 1) & 1][i].w);
                *reinterpret_cast<uint2*>(sAn + row * LDA + c4 * 4) = make_uint2(h2u(h01), h2u(h23));
            }
        }
        // (4) LDG A(c+2) into the freed reg set (latency hidden over next chunk)
        if (c < 2) {
            #pragma unroll
            for (int i = 0; i < 4; i++) {
                int f = tid + i * 512;
                int row = f >> 4, c4 = f & 15;
                aReg[c & 1][i] = *reinterpret_cast<const float4*>(
                    Asrc + (size_t)row * LAYER + (c + 2) * KCH + c4 * 4);
            }
        }

        // (5) MMA ks 2..3
        #pragma unroll
        for (int ks = 2; ks < 4; ks++) {
            wmma::fragment<wmma::matrix_a, 16, 16, 16, __half, wmma::row_major> a0, a1;
            wmma::load_matrix_sync(a0, sA + (wm * 32)      * LDA + ks * 16, LDA);
            wmma::load_matrix_sync(a1, sA + (wm * 32 + 16) * LDA + ks * 16, LDA);
            #pragma unroll
            for (int j = 0; j < 4; j++) {
                wmma::fragment<wmma::matrix_b, 16, 16, 16, __half, wmma::col_major> b;
                wmma::load_matrix_sync(b, sB + ks * 16 + (wn * 64 + j * 16) * LDB, LDB);
                wmma::mma_sync(acc[0][j], a0, b, acc[0][j]);
                wmma::mma_sync(acc[1][j], a1, b, acc[1][j]);
            }
        }

        // (6) close the chunk: B(c+1) landed + all producer writes visible
        if (c < 3) {
            asm volatile("cp.async.wait_group 0;" ::: "memory");
            __syncthreads();
        }
    }

    // ---- epilogue ----
    #pragma unroll
    for (int i = 0; i < 2; i++) {
        const int row0 = mTile * 128 + wm * 32 + i * 16;
        #pragma unroll
        for (int j = 0; j < 4; j++) {
            const int col0 = blk * BSZ + wn * 64 + j * 16;
            wmma::store_matrix_sync(out + (size_t)row0 * LAYER + col0, acc[i][j],
                                    LAYER, wmma::mem_row_major);
        }
    }
}

// ---------------- launch ----------------
extern "C" void kernel_launch(void* const* d_in, const int* in_sizes, int n_in,
                              void* d_out, int out_size) {
    const float* x      = (const float*)d_in[0];
    const float* blocks = (const float*)d_in[1];
    float* out = (float*)d_out;
    (void)in_sizes; (void)n_in; (void)out_size;

    cudaFuncSetAttribute(bd_hmma, cudaFuncAttributeMaxDynamicSharedMemorySize, SM_TOTAL);

    prep_B<<<dim3(8, NBLK), 256>>>(blocks);
    bd_hmma<<<dim3(NROWS / 128, NBLK), 512, SM_TOTAL>>>(x, out);
}

// round 11
// speedup vs baseline: 1.2098x; 1.2098x over previous
#include <cuda_runtime.h>
#include <cuda_fp16.h>
#include <mma.h>
#include <cstdint>

using namespace nvcuda;

// out[8192,4096] = x[8192,4096] @ tanh(blocks*mask); blocks = 16 diag blocks 256x256.
// fp16 single-pass HMMA. Key shape: 256-thread CTAs, 128x128 tile -> 2 CTAs/SM
// (regfile allows it), so co-resident CTAs overlap each other's load and MMA
// phases (round-7 evidence: 49% tensor util at this shape). Twin CTAs covering
// the two N-halves of a block launch adjacently -> the duplicate x read hits L2.
//   Stage 1: tanh + transpose blocks -> g_B [blk][n][k] fp16.
//   Stage 2: K=256 in 4 chunks of 64, double-buffered smem, cp.async B,
//            reg-prefetched A converted fp32->fp16 in-kernel (round-8 loop).

#define LAYER 4096
#define NROWS 8192
#define NBLK  16
#define BSZ   256
#define KCH   64
#define LDA   72   // fp16 elems; 144 B row stride
#define LDB   72

__device__ __align__(16) __half g_B[NBLK * BSZ * BSZ];  // [blk][n][k]

__device__ __forceinline__ uint32_t smem_u32(const void* p) {
    uint32_t a;
    asm("{ .reg .u64 t; cvta.to.shared.u64 t, %1; cvt.u32.u64 %0, t; }" : "=r"(a) : "l"(p));
    return a;
}
__device__ __forceinline__ uint32_t h2u(__half2 h) {
    return *reinterpret_cast<uint32_t*>(&h);
}

// ---------------- Stage 1: tanh + transpose blocks ----------------
__global__ __launch_bounds__(256) void prep_B(const float* __restrict__ blocks) {
    __shared__ float v[32][BSZ + 1];
    const int kt  = blockIdx.x;   // 0..7
    const int blk = blockIdx.y;   // 0..15
    const int tid = threadIdx.x;

    #pragma unroll
    for (int i = 0; i < 32; i++) {
        int idx = tid + i * 256;
        int k = idx >> 8, n = idx & 255;
        v[k][n] = blocks[(size_t)(blk * BSZ + kt * 32 + k) * LAYER + (size_t)(blk * BSZ + n)];
    }
    __syncthreads();

    const int n = tid;
    uint32_t w[16];
    #pragma unroll
    for (int k2 = 0; k2 < 16; k2++) {
        float t0 = tanhf(v[2 * k2][n]);
        float t1 = tanhf(v[2 * k2 + 1][n]);
        w[k2] = h2u(__floats2half2_rn(t0, t1));
    }
    size_t base = (size_t)(blk * BSZ + n) * BSZ + kt * 32;  // [blk][n][k]
    #pragma unroll
    for (int q = 0; q < 4; q++)
        *reinterpret_cast<uint4*>(&g_B[base + q * 8]) =
            make_uint4(w[4 * q], w[4 * q + 1], w[4 * q + 2], w[4 * q + 3]);
}

// ---------------- Stage 2: HMMA GEMM, 2 CTAs/SM ----------------
// dyn smem per CTA: sA0 18432 | sB0 18432 | sA1 18432 | sB1 18432 = 73728 B
#define SMA0 0
#define SMB0 18432
#define SMA1 36864
#define SMB1 55296
#define SM_TOTAL 73728

__global__ void __launch_bounds__(256, 2) bd_hmma(const float* __restrict__ x,
                                                  float* __restrict__ out) {
    extern __shared__ __align__(16) char smem[];
    const uint32_t sbase = smem_u32(smem);
    const int tid = threadIdx.x;
    const int w   = tid >> 5;
    const int wm  = w >> 1;          // 0..3 -> 32-row band
    const int wn  = w & 1;           // 0..1 -> 64-col band
    const int nHalf = blockIdx.x;    // 0..1  (fastest: twin CTAs adjacent -> L2 dedup of x)
    const int mTile = blockIdx.y;    // 0..63
    const int blk   = blockIdx.z;    // 0..15

    const float*  Asrc = x + (size_t)mTile * 128 * LAYER + (size_t)blk * BSZ;
    const __half* Bsrc = g_B + (size_t)blk * BSZ * BSZ + (size_t)nHalf * 128 * BSZ;

    wmma::fragment<wmma::accumulator, 16, 16, 16, float> acc[2][4];
    #pragma unroll
    for (int i = 0; i < 2; i++)
        #pragma unroll
        for (int j = 0; j < 4; j++) wmma::fill_fragment(acc[i][j], 0.0f);

    float4 aReg[8];   // A chunk: 128 rows x 16 float4 = 2048 ids / 256 thr

    // ---- prologue: A(0) -> regs, B(0) -> sB0 via cp.async ----
    #pragma unroll
    for (int i = 0; i < 8; i++) {
        int f = tid + i * 256;
        int row = f >> 4, c4 = f & 15;
        aReg[i] = *reinterpret_cast<const float4*>(Asrc + (size_t)row * LAYER + c4 * 4);
    }
    #pragma unroll
    for (int i = 0; i < 4; i++) {                  // B chunk: 128 n x 8 uint4 = 1024 ids
        int u = tid + i * 256;
        int n = u >> 3, q = u & 7;
        uint32_t dst = sbase + SMB0 + (uint32_t)(n * LDB + q * 8) * 2;
        const __half* src = Bsrc + (size_t)n * BSZ + q * 8;
        asm volatile("cp.async.ca.shared.global [%0], [%1], 16;" :: "r"(dst), "l"(src) : "memory");
    }
    asm volatile("cp.async.commit_group;" ::: "memory");

    for (int c = 0; c < 4; c++) {
        const int buf = c & 1;
        __half* sA = reinterpret_cast<__half*>(smem + (buf ? SMA1 : SMA0));
        __half* sB = reinterpret_cast<__half*>(smem + (buf ? SMB1 : SMB0));

        // ---- convert A regs -> sA (fp16) ----
        #pragma unroll
        for (int i = 0; i < 8; i++) {
            int f = tid + i * 256;
            int row = f >> 4, c4 = f & 15;
            __half2 h01 = __floats2half2_rn(aReg[i].x, aReg[i].y);
            __half2 h23 = __floats2half2_rn(aReg[i].z, aReg[i].w);
            *reinterpret_cast<uint2*>(sA + row * LDA + c4 * 4) = make_uint2(h2u(h01), h2u(h23));
        }

        // ---- prefetch chunk c+1 (A -> regs, B -> other buffer) ----
        if (c < 3) {
            #pragma unroll
            for (int i = 0; i < 8; i++) {
                int f = tid + i * 256;
                int row = f >> 4, c4 = f & 15;
                aReg[i] = *reinterpret_cast<const float4*>(
                    Asrc + (size_t)row * LAYER + (c + 1) * KCH + c4 * 4);
            }
            uint32_t sbB = sbase + (((c + 1) & 1) ? SMB1 : SMB0);
            #pragma unroll
            for (int i = 0; i < 4; i++) {
                int u = tid + i * 256;
                int n = u >> 3, q = u & 7;
                uint32_t dst = sbB + (uint32_t)(n * LDB + q * 8) * 2;
                const __half* src = Bsrc + (size_t)n * BSZ + (c + 1) * KCH + q * 8;
                asm volatile("cp.async.ca.shared.global [%0], [%1], 16;" :: "r"(dst), "l"(src) : "memory");
            }
            asm volatile("cp.async.commit_group;" ::: "memory");
            asm volatile("cp.async.wait_group 1;" ::: "memory");   // chunk c's B done
        } else {
            asm volatile("cp.async.wait_group 0;" ::: "memory");
        }
        __syncthreads();

        // ---- MMA over buf ----
        #pragma unroll
        for (int ks = 0; ks < 4; ks++) {
            wmma::fragment<wmma::matrix_a, 16, 16, 16, __half, wmma::row_major> a0, a1;
            wmma::load_matrix_sync(a0, sA + (wm * 32)      * LDA + ks * 16, LDA);
            wmma::load_matrix_sync(a1, sA + (wm * 32 + 16) * LDA + ks * 16, LDA);
            #pragma unroll
            for (int j = 0; j < 4; j++) {
                wmma::fragment<wmma::matrix_b, 16, 16, 16, __half, wmma::col_major> b;
                wmma::load_matrix_sync(b, sB + ks * 16 + (wn * 64 + j * 16) * LDB, LDB);
                wmma::mma_sync(acc[0][j], a0, b, acc[0][j]);
                wmma::mma_sync(acc[1][j], a1, b, acc[1][j]);
            }
        }
        __syncthreads();
    }

    // ---- epilogue ----
    #pragma unroll
    for (int i = 0; i < 2; i++) {
        const int row0 = mTile * 128 + wm * 32 + i * 16;
        #pragma unroll
        for (int j = 0; j < 4; j++) {
            const int col0 = blk * BSZ + nHalf * 128 + wn * 64 + j * 16;
            wmma::store_matrix_sync(out + (size_t)row0 * LAYER + col0, acc[i][j],
                                    LAYER, wmma::mem_row_major);
        }
    }
}

// ---------------- launch ----------------
extern "C" void kernel_launch(void* const* d_in, const int* in_sizes, int n_in,
                              void* d_out, int out_size) {
    const float* x      = (const float*)d_in[0];
    const float* blocks = (const float*)d_in[1];
    float* out = (float*)d_out;
    (void)in_sizes; (void)n_in; (void)out_size;

    cudaFuncSetAttribute(bd_hmma, cudaFuncAttributeMaxDynamicSharedMemorySize, SM_TOTAL);

    prep_B<<<dim3(8, NBLK), 256>>>(blocks);
    bd_hmma<<<dim3(2, NROWS / 128, NBLK), 256, SM_TOTAL>>>(x, out);
}